// round 3
// baseline (speedup 1.0000x reference)
#include <cuda_runtime.h>
#include <math.h>

// ---------------- scratch (no allocations allowed -> __device__ globals) ----
// qkv: 200704 x 1152 fp32   (925 MB)
// att: 200704 x 384  fp32   (308 MB)
__device__ float g_qkv[200704UL * 1152UL];
__device__ float g_att[200704UL * 384UL];

// ---------------- fp32 tiled GEMM:  C[M][N] = A[M][K] @ W[N][K]^T + bias[N] --
// Both operands are K-contiguous (row-major A, row-major W) -> "NT" gemm.
// BM=BN=128, BK=16, 256 threads, 8x8 micro-tile per thread.
#define BM 128
#define BN 128
#define BK 16
#define SPAD 4

__global__ __launch_bounds__(256) void sgemm_nt(
    const float* __restrict__ A, const float* __restrict__ W,
    const float* __restrict__ bias, float* __restrict__ C,
    int M, int N, int K)
{
    __shared__ float As[BK][BM + SPAD];
    __shared__ float Ws[BK][BN + SPAD];

    const int tid = threadIdx.x;
    const int tx  = tid & 15;   // 16 thread-cols
    const int ty  = tid >> 4;   // 16 thread-rows
    const int bm  = blockIdx.y * BM;
    const int bn  = blockIdx.x * BN;

    float acc[8][8];
#pragma unroll
    for (int i = 0; i < 8; i++)
#pragma unroll
        for (int j = 0; j < 8; j++) acc[i][j] = 0.0f;

    for (int k0 = 0; k0 < K; k0 += BK) {
        // Load 128x16 tiles of A and W, store transposed into smem.
        // 512 float4 per tile, 256 threads -> 2 each.
#pragma unroll
        for (int l = 0; l < 2; l++) {
            int f  = tid + l * 256;        // 0..511
            int r  = f >> 2;               // tile row 0..127
            int c4 = (f & 3) << 2;         // k-offset 0,4,8,12
            float4 av = *(const float4*)(A + (long)(bm + r) * K + k0 + c4);
            As[c4 + 0][r] = av.x; As[c4 + 1][r] = av.y;
            As[c4 + 2][r] = av.z; As[c4 + 3][r] = av.w;
            float4 wv = *(const float4*)(W + (long)(bn + r) * K + k0 + c4);
            Ws[c4 + 0][r] = wv.x; Ws[c4 + 1][r] = wv.y;
            Ws[c4 + 2][r] = wv.z; Ws[c4 + 3][r] = wv.w;
        }
        __syncthreads();

#pragma unroll
        for (int k = 0; k < BK; k++) {
            float a[8], b[8];
            *(float4*)(a)     = *(const float4*)&As[k][ty * 8];
            *(float4*)(a + 4) = *(const float4*)&As[k][ty * 8 + 4];
            *(float4*)(b)     = *(const float4*)&Ws[k][tx * 8];
            *(float4*)(b + 4) = *(const float4*)&Ws[k][tx * 8 + 4];
#pragma unroll
            for (int i = 0; i < 8; i++)
#pragma unroll
                for (int j = 0; j < 8; j++)
                    acc[i][j] += a[i] * b[j];
        }
        __syncthreads();
    }

    // Epilogue: + bias, vectorized store
#pragma unroll
    for (int i = 0; i < 8; i++) {
        int m = bm + ty * 8 + i;
#pragma unroll
        for (int j = 0; j < 8; j += 4) {
            int n = bn + tx * 8 + j;
            float4 o;
            o.x = acc[i][j + 0] + bias[n + 0];
            o.y = acc[i][j + 1] + bias[n + 1];
            o.z = acc[i][j + 2] + bias[n + 2];
            o.w = acc[i][j + 3] + bias[n + 3];
            *(float4*)(C + (long)m * N + n) = o;
        }
    }
}

// ---------------- windowed attention -----------------------------------
// One block per (window b, head h). N=49 tokens, hd=32 (== warp width).
// 256 threads = 8 warps; warp w handles rows i = w, w+8, ...
// Each lane computes logit columns j=lane and j=lane+32 (if < 49),
// exact fp32 softmax with warp shuffles, then PV with lane = head-dim.
__global__ __launch_bounds__(256) void win_attn(
    const float* __restrict__ qkv, const float* __restrict__ mask,
    const float* __restrict__ rpb, float* __restrict__ out)
{
    __shared__ float qs[49][32];
    __shared__ float kt[32][64];   // k transposed [d][j]; cols 49..63 junk
    __shared__ float vs[49][32];
    __shared__ float pbuf[8][52];  // per-warp softmax row

    const int b = blockIdx.x;
    const int h = blockIdx.y;
    const int tid = threadIdx.x;

    const long base = (long)b * 49 * 1152 + h * 32;

    // Load q,k,v tiles (49 x 8 float4 each)
    for (int e = tid; e < 49 * 8; e += 256) {
        int n  = e >> 3;
        int d4 = (e & 7) << 2;
        const float* p = qkv + base + (long)n * 1152 + d4;
        float4 qv = *(const float4*)(p);
        *(float4*)&qs[n][d4] = qv;
        float4 kv = *(const float4*)(p + 384);
        kt[d4 + 0][n] = kv.x; kt[d4 + 1][n] = kv.y;
        kt[d4 + 2][n] = kv.z; kt[d4 + 3][n] = kv.w;
        float4 vv = *(const float4*)(p + 768);
        *(float4*)&vs[n][d4] = vv;
    }
    __syncthreads();

    const int w    = tid >> 5;
    const int lane = tid & 31;
    const float* mrow = mask + (long)(b & 63) * 49 * 49;
    const float scale = 0.17677669529663687f;   // 1/sqrt(32)

    const int j0 = lane, j1 = lane + 32;
    const int rj0 = j0 / 7, cj0 = j0 % 7;
    const int rj1 = j1 / 7, cj1 = j1 % 7;       // only used when j1 < 49

    for (int i = w; i < 49; i += 8) {
        float s0 = 0.0f, s1 = 0.0f;
#pragma unroll
        for (int d = 0; d < 32; d++) {
            float qv = qs[i][d];
            s0 += qv * kt[d][j0];
            s1 += qv * kt[d][j1];
        }
        const int ri = i / 7, ci = i % 7;
        s0 = s0 * scale
           + rpb[((ri - rj0 + 6) * 13 + (ci - cj0 + 6)) * 12 + h]
           + mrow[i * 49 + j0];
        if (j1 < 49) {
            s1 = s1 * scale
               + rpb[((ri - rj1 + 6) * 13 + (ci - cj1 + 6)) * 12 + h]
               + mrow[i * 49 + j1];
        } else {
            s1 = -INFINITY;
        }

        // warp max
        float mx = fmaxf(s0, s1);
#pragma unroll
        for (int off = 16; off > 0; off >>= 1)
            mx = fmaxf(mx, __shfl_xor_sync(0xffffffffu, mx, off));

        float p0 = expf(s0 - mx);
        float p1 = (j1 < 49) ? expf(s1 - mx) : 0.0f;
        float sum = p0 + p1;
#pragma unroll
        for (int off = 16; off > 0; off >>= 1)
            sum += __shfl_xor_sync(0xffffffffu, sum, off);
        float inv = 1.0f / sum;

        pbuf[w][j0] = p0 * inv;
        if (j1 < 49) pbuf[w][j1] = p1 * inv;
        __syncwarp();

        // out[i][lane] = sum_j P[i][j] * v[j][lane]
        float acc = 0.0f;
#pragma unroll
        for (int j = 0; j < 49; j++)
            acc += pbuf[w][j] * vs[j][lane];

        out[(long)(b * 49 + i) * 384 + h * 32 + lane] = acc;
        __syncwarp();
    }
}

// ---------------- launch ----------------------------------------------
extern "C" void kernel_launch(void* const* d_in, const int* in_sizes, int n_in,
                              void* d_out, int out_size)
{
    const float* x      = (const float*)d_in[0];
    const float* mask   = (const float*)d_in[1];
    const float* qkv_w  = (const float*)d_in[2];
    const float* qkv_b  = (const float*)d_in[3];
    const float* proj_w = (const float*)d_in[4];
    const float* proj_b = (const float*)d_in[5];
    const float* rpb    = (const float*)d_in[6];
    float* out = (float*)d_out;

    float *qkv, *att;
    cudaGetSymbolAddress((void**)&qkv, g_qkv);
    cudaGetSymbolAddress((void**)&att, g_att);

    // 1) qkv = x @ qkv_w^T + qkv_b          (M=200704, N=1152, K=384)
    sgemm_nt<<<dim3(1152 / BN, 200704 / BM), 256>>>(x, qkv_w, qkv_b, qkv,
                                                    200704, 1152, 384);
    // 2) windowed attention -> att (200704 x 384, [b,n,(h,d)] layout)
    win_attn<<<dim3(4096, 12), 256>>>(qkv, mask, rpb, att);

    // 3) out = att @ proj_w^T + proj_b      (M=200704, N=384, K=384)
    sgemm_nt<<<dim3(384 / BN, 200704 / BM), 256>>>(att, proj_w, proj_b, out,
                                                   200704, 384, 384);
}

// round 5
// speedup vs baseline: 1.8710x; 1.8710x over previous
#include <cuda_runtime.h>
#include <math.h>
#include <stdint.h>

// ---------------- scratch (no allocations allowed -> __device__ globals) ----
__device__ float g_qkv[200704UL * 1152UL];   // 925 MB
__device__ float g_att[200704UL * 384UL];    // 308 MB

static __device__ __forceinline__ uint32_t s2u(const void* p) {
    return (uint32_t)__cvta_generic_to_shared(p);
}

static __device__ __forceinline__ uint32_t f2tf32(float x) {
    uint32_t t;
    asm("cvt.rna.tf32.f32 %0, %1;" : "=r"(t) : "f"(x));
    return t;
}

static __device__ __forceinline__ void ldsm4(uint32_t r[4], uint32_t addr) {
    asm volatile("ldmatrix.sync.aligned.m8n8.x4.shared.b16 {%0,%1,%2,%3}, [%4];"
                 : "=r"(r[0]), "=r"(r[1]), "=r"(r[2]), "=r"(r[3]) : "r"(addr));
}

static __device__ __forceinline__ void mma_tf32(float c[4], const uint32_t a[4],
                                                uint32_t b0, uint32_t b1) {
    asm volatile(
        "mma.sync.aligned.m16n8k8.row.col.f32.tf32.tf32.f32 "
        "{%0,%1,%2,%3}, {%4,%5,%6,%7}, {%8,%9}, {%0,%1,%2,%3};"
        : "+f"(c[0]), "+f"(c[1]), "+f"(c[2]), "+f"(c[3])
        : "r"(a[0]), "r"(a[1]), "r"(a[2]), "r"(a[3]), "r"(b0), "r"(b1));
}

// ---------------- tf32 tensor-core GEMM:  C = A[M,K] @ W[N,K]^T + bias -------
// 128x128 CTA tile, BK=32, 512 threads = 16 warps (4x4), 32x32 warp tile.
// smem rows padded to 36 words -> conflict-free LDSM (36 mod 32 = 4).
__global__ __launch_bounds__(512) void tf32_gemm_nt(
    const float* __restrict__ A, const float* __restrict__ W,
    const float* __restrict__ bias, float* __restrict__ C,
    int M, int N, int K)
{
    __shared__ float As[128][36];
    __shared__ float Ws[128][36];

    const int tid  = threadIdx.x;
    const int bm   = blockIdx.y * 128;
    const int bn   = blockIdx.x * 128;
    const int lane = tid & 31;
    const int wid  = tid >> 5;
    const int wm   = (wid & 3) * 32;    // warp row offset
    const int wn   = (wid >> 2) * 32;   // warp col offset

    // ldmatrix source coordinates (per-lane)
    const int a_row = wm + (lane & 15);
    const int a_k   = (lane >> 4) << 2;                 // 0 or 4
    const int b_row = wn + (lane & 7) + ((lane & 16) >> 1);  // +8 when lane>=16
    const int b_k   = (lane & 8) >> 1;                  // 0 or 4

    // gmem staging coordinates: 1024 float4 per tile / 512 threads = 2 each
    const int r0 = tid >> 3,           c0 = (tid & 7) << 2;
    const int r1 = (tid + 512) >> 3,   c1 = c0;

    float acc[2][4][4];
#pragma unroll
    for (int mt = 0; mt < 2; mt++)
#pragma unroll
        for (int nt = 0; nt < 4; nt++)
#pragma unroll
            for (int i = 0; i < 4; i++) acc[mt][nt][i] = 0.0f;

    const int KT = K >> 5;                // K / 32
    float4 sA0, sA1, sW0, sW1;

    // prologue: stage first tile
    sA0 = *(const float4*)(A + (size_t)(bm + r0) * K + c0);
    sA1 = *(const float4*)(A + (size_t)(bm + r1) * K + c1);
    sW0 = *(const float4*)(W + (size_t)(bn + r0) * K + c0);
    sW1 = *(const float4*)(W + (size_t)(bn + r1) * K + c1);

    for (int it = 0; it < KT; it++) {
        // store staged tile (tf32-rounded)
        *(uint4*)&As[r0][c0] = make_uint4(f2tf32(sA0.x), f2tf32(sA0.y), f2tf32(sA0.z), f2tf32(sA0.w));
        *(uint4*)&As[r1][c1] = make_uint4(f2tf32(sA1.x), f2tf32(sA1.y), f2tf32(sA1.z), f2tf32(sA1.w));
        *(uint4*)&Ws[r0][c0] = make_uint4(f2tf32(sW0.x), f2tf32(sW0.y), f2tf32(sW0.z), f2tf32(sW0.w));
        *(uint4*)&Ws[r1][c1] = make_uint4(f2tf32(sW1.x), f2tf32(sW1.y), f2tf32(sW1.z), f2tf32(sW1.w));
        __syncthreads();

        // prefetch next tile to registers while computing
        if (it + 1 < KT) {
            int k0 = (it + 1) << 5;
            sA0 = *(const float4*)(A + (size_t)(bm + r0) * K + k0 + c0);
            sA1 = *(const float4*)(A + (size_t)(bm + r1) * K + k0 + c1);
            sW0 = *(const float4*)(W + (size_t)(bn + r0) * K + k0 + c0);
            sW1 = *(const float4*)(W + (size_t)(bn + r1) * K + k0 + c1);
        }

#pragma unroll
        for (int s = 0; s < 4; s++) {
            const int k8 = s << 3;
            uint32_t a[2][4], b[2][4];
#pragma unroll
            for (int mt = 0; mt < 2; mt++)
                ldsm4(a[mt], s2u(&As[a_row + mt * 16][k8 + a_k]));
#pragma unroll
            for (int p = 0; p < 2; p++)
                ldsm4(b[p], s2u(&Ws[b_row + p * 16][k8 + b_k]));
            // b[p] = { ntile(2p).b0, ntile(2p).b1, ntile(2p+1).b0, ntile(2p+1).b1 }
#pragma unroll
            for (int mt = 0; mt < 2; mt++)
#pragma unroll
                for (int nt = 0; nt < 4; nt++)
                    mma_tf32(acc[mt][nt], a[mt],
                             b[nt >> 1][(nt & 1) * 2], b[nt >> 1][(nt & 1) * 2 + 1]);
        }
        __syncthreads();
    }

    // epilogue: c0,c1 -> (row qr, cols qc,qc+1); c2,c3 -> row qr+8
    const int qr = lane >> 2;
    const int qc = (lane & 3) * 2;
#pragma unroll
    for (int mt = 0; mt < 2; mt++) {
        const int row = bm + wm + mt * 16 + qr;
#pragma unroll
        for (int nt = 0; nt < 4; nt++) {
            const int col = bn + wn + nt * 8 + qc;
            const float bx = bias[col], by = bias[col + 1];
            float2 lo = make_float2(acc[mt][nt][0] + bx, acc[mt][nt][1] + by);
            float2 hi = make_float2(acc[mt][nt][2] + bx, acc[mt][nt][3] + by);
            *(float2*)(C + (size_t)row * N + col)       = lo;
            *(float2*)(C + (size_t)(row + 8) * N + col) = hi;
        }
    }
}

// ---------------- windowed attention (unchanged, exact fp32) ---------------
__global__ __launch_bounds__(256) void win_attn(
    const float* __restrict__ qkv, const float* __restrict__ mask,
    const float* __restrict__ rpb, float* __restrict__ out)
{
    __shared__ float qs[49][32];
    __shared__ float kt[32][64];
    __shared__ float vs[49][32];
    __shared__ float pbuf[8][52];

    const int b = blockIdx.x;
    const int h = blockIdx.y;
    const int tid = threadIdx.x;

    const long base = (long)b * 49 * 1152 + h * 32;

    for (int e = tid; e < 49 * 8; e += 256) {
        int n  = e >> 3;
        int d4 = (e & 7) << 2;
        const float* p = qkv + base + (long)n * 1152 + d4;
        float4 qv = *(const float4*)(p);
        *(float4*)&qs[n][d4] = qv;
        float4 kv = *(const float4*)(p + 384);
        kt[d4 + 0][n] = kv.x; kt[d4 + 1][n] = kv.y;
        kt[d4 + 2][n] = kv.z; kt[d4 + 3][n] = kv.w;
        float4 vv = *(const float4*)(p + 768);
        *(float4*)&vs[n][d4] = vv;
    }
    __syncthreads();

    const int w    = tid >> 5;
    const int lane = tid & 31;
    const float* mrow = mask + (long)(b & 63) * 49 * 49;
    const float scale = 0.17677669529663687f;

    const int j0 = lane, j1 = lane + 32;
    const int rj0 = j0 / 7, cj0 = j0 % 7;
    const int rj1 = j1 / 7, cj1 = j1 % 7;

    for (int i = w; i < 49; i += 8) {
        float s0 = 0.0f, s1 = 0.0f;
#pragma unroll
        for (int d = 0; d < 32; d++) {
            float qv = qs[i][d];
            s0 += qv * kt[d][j0];
            s1 += qv * kt[d][j1];
        }
        const int ri = i / 7, ci = i % 7;
        s0 = s0 * scale
           + rpb[((ri - rj0 + 6) * 13 + (ci - cj0 + 6)) * 12 + h]
           + mrow[i * 49 + j0];
        if (j1 < 49) {
            s1 = s1 * scale
               + rpb[((ri - rj1 + 6) * 13 + (ci - cj1 + 6)) * 12 + h]
               + mrow[i * 49 + j1];
        } else {
            s1 = -INFINITY;
        }

        float mx = fmaxf(s0, s1);
#pragma unroll
        for (int off = 16; off > 0; off >>= 1)
            mx = fmaxf(mx, __shfl_xor_sync(0xffffffffu, mx, off));

        float p0 = expf(s0 - mx);
        float p1 = (j1 < 49) ? expf(s1 - mx) : 0.0f;
        float sum = p0 + p1;
#pragma unroll
        for (int off = 16; off > 0; off >>= 1)
            sum += __shfl_xor_sync(0xffffffffu, sum, off);
        float inv = 1.0f / sum;

        pbuf[w][j0] = p0 * inv;
        if (j1 < 49) pbuf[w][j1] = p1 * inv;
        __syncwarp();

        float acc = 0.0f;
#pragma unroll
        for (int j = 0; j < 49; j++)
            acc += pbuf[w][j] * vs[j][lane];

        out[(long)(b * 49 + i) * 384 + h * 32 + lane] = acc;
        __syncwarp();
    }
}

// ---------------- launch ----------------------------------------------
extern "C" void kernel_launch(void* const* d_in, const int* in_sizes, int n_in,
                              void* d_out, int out_size)
{
    const float* x      = (const float*)d_in[0];
    const float* mask   = (const float*)d_in[1];
    const float* qkv_w  = (const float*)d_in[2];
    const float* qkv_b  = (const float*)d_in[3];
    const float* proj_w = (const float*)d_in[4];
    const float* proj_b = (const float*)d_in[5];
    const float* rpb    = (const float*)d_in[6];
    float* out = (float*)d_out;

    float *qkv, *att;
    cudaGetSymbolAddress((void**)&qkv, g_qkv);
    cudaGetSymbolAddress((void**)&att, g_att);

    // 1) qkv = x @ qkv_w^T + qkv_b          (M=200704, N=1152, K=384)
    tf32_gemm_nt<<<dim3(1152 / 128, 200704 / 128), 512>>>(x, qkv_w, qkv_b, qkv,
                                                          200704, 1152, 384);
    // 2) windowed attention -> att (200704 x 384, [b,n,(h,d)] layout)
    win_attn<<<dim3(4096, 12), 256>>>(qkv, mask, rpb, att);

    // 3) out = att @ proj_w^T + proj_b      (M=200704, N=384, K=384)
    tf32_gemm_nt<<<dim3(384 / 128, 200704 / 128), 512>>>(att, proj_w, proj_b, out,
                                                         200704, 384, 384);
}